// round 2
// baseline (speedup 1.0000x reference)
#include <cuda_runtime.h>

#define Bc 2
#define Lc 2048
#define Hc 8
#define Dc 64
#define HD (Hc*Dc)          // 512 floats per sequence position
#define NCHUNK 128
#define CHUNK (Lc/NCHUNK)   // 16
#define GPB 520             // groups per (b,h): 65 residues * 8 groups of 4 rows
#define NWARP (Bc*Hc*GPB)   // 8320 warps total

// Scratch (device globals — no allocation allowed)
__device__ float g_prefix[Bc*Lc*Hc*Dc];        // inclusive prefix sums of V along L
__device__ float g_chunk[Bc*Hc*NCHUNK*Dc];     // per-chunk V sums

// ---------------- Prefix-sum of V over sequence dim (2 kernels) -------------

__global__ void prefix_pass1(const float* __restrict__ V) {
    int blk = blockIdx.x;            // bh*NCHUNK + c
    int c  = blk & (NCHUNK-1);
    int bh = blk >> 7;
    int d = threadIdx.x;
    int base = (bh>>3)*(Lc*HD) + (bh&7)*Dc + (c*CHUNK)*HD + d;
    float s = 0.f;
    #pragma unroll
    for (int rr = 0; rr < CHUNK; ++rr) s += V[base + rr*HD];
    g_chunk[blk*Dc + d] = s;
}

__global__ void prefix_pass2(const float* __restrict__ V) {
    int blk = blockIdx.x;
    int c  = blk & (NCHUNK-1);
    int bh = blk >> 7;
    int d = threadIdx.x;
    // exclusive offset for this chunk: sum of earlier chunk sums (recomputed per block)
    float run = 0.f;
    for (int cp = 0; cp < c; ++cp)
        run += g_chunk[(bh*NCHUNK + cp)*Dc + d];
    int base = (bh>>3)*(Lc*HD) + (bh&7)*Dc + (c*CHUNK)*HD + d;
    #pragma unroll
    for (int rr = 0; rr < CHUNK; ++rr) {
        run += V[base + rr*HD];
        g_prefix[base + rr*HD] = run;   // inclusive prefix
    }
}

// ---------------- Main sparse-attention kernel -------------------------------
// Warp owns 4 rows at the same residue mod 65: i_k = i0 + 65k (strided taps are
// nested across these rows -> each tap row loaded once, used by all 4 rows).
// Lane layout: jg = lane&3 selects the key within a 4-key batch;
//              sub = lane>>2 selects a 16B slice of D (A: dims 4*sub, B: 32+4*sub).
// Softmax: no max subtraction (scores bounded); baseline weight of the
// zero-score non-selected entries folded in via (w-1) + prefix-sum-of-V.

__global__ __launch_bounds__(256, 2)
void dozer_main(const float* __restrict__ Q, const float* __restrict__ K,
                const float* __restrict__ V, float* __restrict__ O) {
    const int lane = threadIdx.x & 31;
    const int jg = lane & 3;
    const int sub = lane >> 2;

    int gw = blockIdx.x * 8 + (threadIdx.x >> 5);   // grid is exactly NWARP/8
    int bh = gw / GPB;
    int g  = gw - bh*GPB;
    int r   = g % 65;
    int grp = g / 65;
    int i0 = r + 260*grp;                       // first anchor row
    int kmax = (Lc - 1 - i0)/65 + 1; if (kmax > 4) kmax = 4;
    int base = (bh>>3)*(Lc*HD) + (bh&7)*Dc;

    const float4* Q4 = (const float4*)(Q + base);
    const float4* K4 = (const float4*)(K + base);
    const float4* V4 = (const float4*)(V + base);

    float4 qA[4], qB[4], ovA[4], ovB[4];
    float accw[4];
    const float4 z4 = make_float4(0.f,0.f,0.f,0.f);
    #pragma unroll
    for (int k = 0; k < 4; ++k) {
        ovA[k] = z4; ovB[k] = z4; accw[k] = 0.f;
        if (k < kmax) {
            int ik = i0 + 65*k;
            qA[k] = Q4[ik*128 + sub];
            qB[k] = Q4[ik*128 + 8 + sub];
        } else { qA[k] = z4; qB[k] = z4; }   // zero q => zero contribution
    }

    // ---- local bands (per row, 17 keys, 4 keys/iteration) ----
    #pragma unroll
    for (int k = 0; k < 4; ++k) {
        if (k >= kmax) break;
        int ik = i0 + 65*k;
        int lo = ik > 16 ? ik - 16 : 0;
        int nk = ik - lo + 1;
        for (int it0 = 0; it0 < nk; it0 += 4) {
            int idx = it0 + jg;
            bool act = idx < nk;
            int j = act ? (lo + idx) : ik;
            float4 kA = K4[j*128 + sub];
            float4 kB = K4[j*128 + 8 + sub];
            float x = qA[k].x*kA.x + qA[k].y*kA.y + qA[k].z*kA.z + qA[k].w*kA.w
                    + qB[k].x*kB.x + qB[k].y*kB.y + qB[k].z*kB.z + qB[k].w*kB.w;
            x += __shfl_xor_sync(0xffffffffu, x, 4);
            x += __shfl_xor_sync(0xffffffffu, x, 8);
            x += __shfl_xor_sync(0xffffffffu, x, 16);
            float w = act ? (__expf(0.125f*x) - 1.0f) : 0.f;
            accw[k] += w;
            float4 vA = V4[j*128 + sub];
            float4 vB = V4[j*128 + 8 + sub];
            ovA[k].x += w*vA.x; ovA[k].y += w*vA.y; ovA[k].z += w*vA.z; ovA[k].w += w*vA.w;
            ovB[k].x += w*vB.x; ovB[k].y += w*vB.y; ovB[k].z += w*vB.z; ovB[k].w += w*vB.w;
        }
    }

    // ---- strided taps, shared across the 4 anchor rows ----
    // tap s: j = i0 + 65*(kmax-2-s), s = 0..ntap-1 (descending; covers anchors
    // below the deepest row, then rows below i0 down to the residue base).
    // tap s feeds row k iff s >= kmax-1-k.
    int ntap = (kmax - 1) + 4*grp;
    for (int s0 = 0; s0 < ntap; s0 += 4) {
        int s = s0 + jg;
        bool any = s < ntap;
        int j = any ? (i0 + 65*(kmax - 2 - s)) : i0;
        float4 kA = K4[j*128 + sub];
        float4 kB = K4[j*128 + 8 + sub];
        float4 vA = V4[j*128 + sub];
        float4 vB = V4[j*128 + 8 + sub];
        #pragma unroll
        for (int k = 0; k < 4; ++k) {
            float x = qA[k].x*kA.x + qA[k].y*kA.y + qA[k].z*kA.z + qA[k].w*kA.w
                    + qB[k].x*kB.x + qB[k].y*kB.y + qB[k].z*kB.z + qB[k].w*kB.w;
            x += __shfl_xor_sync(0xffffffffu, x, 4);
            x += __shfl_xor_sync(0xffffffffu, x, 8);
            x += __shfl_xor_sync(0xffffffffu, x, 16);
            bool a = any && (s >= kmax - 1 - k);
            float w = a ? (__expf(0.125f*x) - 1.0f) : 0.f;
            accw[k] += w;
            ovA[k].x += w*vA.x; ovA[k].y += w*vA.y; ovA[k].z += w*vA.z; ovA[k].w += w*vA.w;
            ovB[k].x += w*vB.x; ovB[k].y += w*vB.y; ovB[k].z += w*vB.z; ovB[k].w += w*vB.w;
        }
    }

    // ---- epilogue: fold baseline via prefix sums, normalize, write ----
    #pragma unroll
    for (int k = 0; k < 4; ++k) {
        if (k >= kmax) break;
        int ik = i0 + 65*k;
        float aw = accw[k];
        aw += __shfl_xor_sync(0xffffffffu, aw, 1);
        aw += __shfl_xor_sync(0xffffffffu, aw, 2);
        float4 oA = ovA[k], oB = ovB[k];
        oA.x += __shfl_xor_sync(0xffffffffu, oA.x, 1); oA.x += __shfl_xor_sync(0xffffffffu, oA.x, 2);
        oA.y += __shfl_xor_sync(0xffffffffu, oA.y, 1); oA.y += __shfl_xor_sync(0xffffffffu, oA.y, 2);
        oA.z += __shfl_xor_sync(0xffffffffu, oA.z, 1); oA.z += __shfl_xor_sync(0xffffffffu, oA.z, 2);
        oA.w += __shfl_xor_sync(0xffffffffu, oA.w, 1); oA.w += __shfl_xor_sync(0xffffffffu, oA.w, 2);
        oB.x += __shfl_xor_sync(0xffffffffu, oB.x, 1); oB.x += __shfl_xor_sync(0xffffffffu, oB.x, 2);
        oB.y += __shfl_xor_sync(0xffffffffu, oB.y, 1); oB.y += __shfl_xor_sync(0xffffffffu, oB.y, 2);
        oB.z += __shfl_xor_sync(0xffffffffu, oB.z, 1); oB.z += __shfl_xor_sync(0xffffffffu, oB.z, 2);
        oB.w += __shfl_xor_sync(0xffffffffu, oB.w, 1); oB.w += __shfl_xor_sync(0xffffffffu, oB.w, 2);
        float inv = __fdividef(1.0f, aw + (float)(ik + 1));
        if (jg == 0) {
            const float4* P4 = (const float4*)(g_prefix + base);
            float4 pA = P4[ik*128 + sub];
            float4 pB = P4[ik*128 + 8 + sub];
            float4 rA = make_float4((oA.x+pA.x)*inv, (oA.y+pA.y)*inv,
                                    (oA.z+pA.z)*inv, (oA.w+pA.w)*inv);
            float4 rB = make_float4((oB.x+pB.x)*inv, (oB.y+pB.y)*inv,
                                    (oB.z+pB.z)*inv, (oB.w+pB.w)*inv);
            float4* O4 = (float4*)(O + base);
            O4[ik*128 + sub] = rA;
            O4[ik*128 + 8 + sub] = rB;
        }
    }
}

// ---------------- Launch -----------------------------------------------------

extern "C" void kernel_launch(void* const* d_in, const int* in_sizes, int n_in,
                              void* d_out, int out_size) {
    const float* Q = (const float*)d_in[0];
    const float* K = (const float*)d_in[1];
    const float* V = (const float*)d_in[2];
    // d_in[3] = attn_mask (causal, structure known at compile time, unused)
    float* O = (float*)d_out;

    prefix_pass1<<<Bc*Hc*NCHUNK, Dc>>>(V);
    prefix_pass2<<<Bc*Hc*NCHUNK, Dc>>>(V);
    dozer_main<<<NWARP/8, 256>>>(Q, K, V, O);
}